// round 1
// baseline (speedup 1.0000x reference)
#include <cuda_runtime.h>
#include <cstdint>

#define NROWS 8192
#define DDIM  1024
#define MARGIN_F 0.05f

// ---------------- scratch (no allocations allowed) ----------------
#define NSPLIT 4
__device__ float g_pos[NROWS];
__device__ float g_pval[NSPLIT * NROWS];
__device__ int   g_pidx[NSPLIT * NROWS];
__device__ float g_terms[NROWS];

#define NEG_INF (__int_as_float(0xff800000))

// ---------------- kernel 1: pos_sim (warp per row) ----------------
__global__ void k_pos(const float* __restrict__ x, const float* __restrict__ y) {
    int row  = blockIdx.x * 8 + (threadIdx.x >> 5);
    int lane = threadIdx.x & 31;
    const float4* xr = (const float4*)(x + (size_t)row * DDIM);
    const float4* yr = (const float4*)(y + (size_t)row * DDIM);
    float s = 0.f;
#pragma unroll
    for (int i = lane; i < DDIM / 4; i += 32) {
        float4 a = xr[i], b = yr[i];
        s += a.x * b.x + a.y * b.y + a.z * b.z + a.w * b.w;
    }
#pragma unroll
    for (int o = 16; o; o >>= 1) s += __shfl_xor_sync(0xffffffffu, s, o);
    if (lane == 0) g_pos[row] = s;
}

// ---------------- kernel 2: fused GEMM + masked argmax ----------------
// C = X @ Y^T over a 128-row band, column-split across blockIdx.y.
// Per-row running (best value, first index) kept in smem; masked entries
// contribute value -1.0f with their own column index (exact argmax semantics).
#define BM 128
#define BN 128
#define BK 16
#define TM 8
#define TN 8
#define COLS_PER_SPLIT (NROWS / NSPLIT)

__global__ __launch_bounds__(256, 2)
void k_gemm_argmax(const float* __restrict__ X, const float* __restrict__ Y) {
    __shared__ float As[BK][BM];
    __shared__ float Bs[BK][BN];
    __shared__ float s_pos[BM];
    __shared__ float s_bv[BM];
    __shared__ int   s_bi[BM];

    const int tid = threadIdx.x;
    const int tx = tid & 15;        // 16 threads cover a row's 128 cols
    const int ty = tid >> 4;
    const int row0 = blockIdx.x * BM;
    const int col_base = blockIdx.y * COLS_PER_SPLIT;

    if (tid < BM) {
        s_pos[tid] = g_pos[row0 + tid];
        s_bv[tid]  = NEG_INF;
        s_bi[tid]  = 0x7fffffff;
    }
    __syncthreads();

    for (int ct = 0; ct < COLS_PER_SPLIT; ct += BN) {
        const int col0 = col_base + ct;

        float acc[TM][TN];
#pragma unroll
        for (int i = 0; i < TM; i++)
#pragma unroll
            for (int j = 0; j < TN; j++) acc[i][j] = 0.f;

        for (int kt = 0; kt < DDIM; kt += BK) {
            // load tiles: coalesced float4 gmem reads, transposed STS
#pragma unroll
            for (int it = 0; it < 2; it++) {
                int lin = tid + it * 256;           // 0..511
                int r  = lin >> 2;
                int c4 = (lin & 3) << 2;
                float4 va = *(const float4*)(X + (size_t)(row0 + r) * DDIM + kt + c4);
                As[c4 + 0][r] = va.x; As[c4 + 1][r] = va.y;
                As[c4 + 2][r] = va.z; As[c4 + 3][r] = va.w;
                float4 vb = *(const float4*)(Y + (size_t)(col0 + r) * DDIM + kt + c4);
                Bs[c4 + 0][r] = vb.x; Bs[c4 + 1][r] = vb.y;
                Bs[c4 + 2][r] = vb.z; Bs[c4 + 3][r] = vb.w;
            }
            __syncthreads();

#pragma unroll
            for (int k = 0; k < BK; k++) {
                float a[TM], b[TN];
                *(float4*)&a[0] = *(const float4*)&As[k][ty * TM];
                *(float4*)&a[4] = *(const float4*)&As[k][ty * TM + 4];
                *(float4*)&b[0] = *(const float4*)&Bs[k][tx * TN];
                *(float4*)&b[4] = *(const float4*)&Bs[k][tx * TN + 4];
#pragma unroll
                for (int i = 0; i < TM; i++)
#pragma unroll
                    for (int j = 0; j < TN; j++)
                        acc[i][j] = fmaf(a[i], b[j], acc[i][j]);
            }
            __syncthreads();
        }

        // epilogue: mask + per-row argmax over this 128x128 tile
#pragma unroll
        for (int i = 0; i < TM; i++) {
            const int rloc = ty * TM + i;
            const int row  = row0 + rloc;
            const float p  = s_pos[rloc];
            float bv = NEG_INF;
            int   bi = 0x7fffffff;
#pragma unroll
            for (int j = 0; j < TN; j++) {
                int col = col0 + tx * TN + j;
                float s = acc[i][j];
                float v = (col == row || s > p) ? -1.0f : s;
                if (v > bv || (v == bv && col < bi)) { bv = v; bi = col; }
            }
            // reduce across the 16 lanes sharing this row (lane segments of 16)
#pragma unroll
            for (int o = 8; o; o >>= 1) {
                float ov = __shfl_down_sync(0xffffffffu, bv, o, 16);
                int   oi = __shfl_down_sync(0xffffffffu, bi, o, 16);
                if (ov > bv || (ov == bv && oi < bi)) { bv = ov; bi = oi; }
            }
            if (tx == 0) {
                if (bv > s_bv[rloc] || (bv == s_bv[rloc] && bi < s_bi[rloc])) {
                    s_bv[rloc] = bv; s_bi[rloc] = bi;
                }
            }
        }
        __syncthreads();
    }

    if (tid < BM) {
        g_pval[blockIdx.y * NROWS + row0 + tid] = s_bv[tid];
        g_pidx[blockIdx.y * NROWS + row0 + tid] = s_bi[tid];
    }
}

// ---------------- kernel 3: merge splits, gather dot, per-row loss term ----------------
__global__ void k_neg(const float* __restrict__ x, const float* __restrict__ y) {
    int row  = blockIdx.x * 8 + (threadIdx.x >> 5);
    int lane = threadIdx.x & 31;

    // merge NSPLIT partials in ascending column order (preserves first-index ties)
    float bv = NEG_INF;
    int   bi = 0x7fffffff;
#pragma unroll
    for (int s = 0; s < NSPLIT; s++) {
        float v = g_pval[s * NROWS + row];
        int   i = g_pidx[s * NROWS + row];
        if (v > bv || (v == bv && i < bi)) { bv = v; bi = i; }
    }

    const float4* xr = (const float4*)(x + (size_t)row * DDIM);
    const float4* yr = (const float4*)(y + (size_t)bi * DDIM);
    float s = 0.f;
#pragma unroll
    for (int i = lane; i < DDIM / 4; i += 32) {
        float4 a = xr[i], b = yr[i];
        s += a.x * b.x + a.y * b.y + a.z * b.z + a.w * b.w;
    }
#pragma unroll
    for (int o = 16; o; o >>= 1) s += __shfl_xor_sync(0xffffffffu, s, o);
    if (lane == 0) g_terms[row] = fmaxf(0.f, MARGIN_F - g_pos[row] + s);
}

// ---------------- kernel 4: deterministic mean reduction ----------------
__global__ void k_reduce(float* __restrict__ out) {
    __shared__ float sm[1024];
    int tid = threadIdx.x;
    float s = 0.f;
#pragma unroll
    for (int i = 0; i < NROWS / 1024; i++) s += g_terms[tid + i * 1024];
    sm[tid] = s;
    __syncthreads();
    for (int o = 512; o; o >>= 1) {
        if (tid < o) sm[tid] += sm[tid + o];
        __syncthreads();
    }
    if (tid == 0) out[0] = sm[0] / (float)NROWS;
}

// ---------------- launch ----------------
extern "C" void kernel_launch(void* const* d_in, const int* in_sizes, int n_in,
                              void* d_out, int out_size) {
    const float* x = (const float*)d_in[0];
    const float* y = (const float*)d_in[1];
    float* out = (float*)d_out;

    k_pos<<<NROWS / 8, 256>>>(x, y);
    dim3 grid(NROWS / BM, NSPLIT);
    k_gemm_argmax<<<grid, 256>>>(x, y);
    k_neg<<<NROWS / 8, 256>>>(x, y);
    k_reduce<<<1, 1024>>>(out);
}

// round 3
// speedup vs baseline: 2.4814x; 2.4814x over previous
#include <cuda_runtime.h>
#include <cuda_bf16.h>
#include <cstdint>

#define NROWS 8192
#define DDIM  1024
#define MARGIN_F 0.05f
#define NEG_INF (__int_as_float(0xff800000))

#define BM 128
#define BN 128
#define BK 32
#define NITER (3 * DDIM / BK)        // 96
#define NTILE_N (NROWS / BN)         // 64
#define LDS_PAD 40                    // bf16 elems per smem row (pad 32 -> 40)

// ---------------- device scratch ----------------
__device__ __nv_bfloat16 g_xh[(size_t)NROWS * DDIM];
__device__ __nv_bfloat16 g_xl[(size_t)NROWS * DDIM];
__device__ __nv_bfloat16 g_yh[(size_t)NROWS * DDIM];
__device__ __nv_bfloat16 g_yl[(size_t)NROWS * DDIM];
__device__ float g_pos[NROWS];
__device__ float g_pval[(size_t)NTILE_N * NROWS];
__device__ int   g_pidx[(size_t)NTILE_N * NROWS];
__device__ float g_terms[NROWS];

// ---------------- asm helpers ----------------
__device__ __forceinline__ void cp16(uint32_t sdst, const void* gsrc) {
    asm volatile("cp.async.cg.shared.global [%0], [%1], 16;" :: "r"(sdst), "l"(gsrc) : "memory");
}
__device__ __forceinline__ void cp_commit() { asm volatile("cp.async.commit_group;" ::: "memory"); }
__device__ __forceinline__ void cp_wait0()  { asm volatile("cp.async.wait_group 0;" ::: "memory"); }

__device__ __forceinline__ void ldsm_x4(uint32_t& a0, uint32_t& a1, uint32_t& a2, uint32_t& a3, uint32_t addr) {
    asm volatile("ldmatrix.sync.aligned.m8n8.x4.shared.b16 {%0,%1,%2,%3}, [%4];"
        : "=r"(a0), "=r"(a1), "=r"(a2), "=r"(a3) : "r"(addr));
}
__device__ __forceinline__ void ldsm_x2(uint32_t& b0, uint32_t& b1, uint32_t addr) {
    asm volatile("ldmatrix.sync.aligned.m8n8.x2.shared.b16 {%0,%1}, [%2];"
        : "=r"(b0), "=r"(b1) : "r"(addr));
}
__device__ __forceinline__ void mma_bf16(float* c, uint32_t a0, uint32_t a1, uint32_t a2, uint32_t a3,
                                         uint32_t b0, uint32_t b1) {
    asm volatile("mma.sync.aligned.m16n8k16.row.col.f32.bf16.bf16.f32 "
        "{%0,%1,%2,%3}, {%4,%5,%6,%7}, {%8,%9}, {%0,%1,%2,%3};"
        : "+f"(c[0]), "+f"(c[1]), "+f"(c[2]), "+f"(c[3])
        : "r"(a0), "r"(a1), "r"(a2), "r"(a3), "r"(b0), "r"(b1));
}

// ---------------- kernel 0: hi/lo bf16 split ----------------
__global__ void k_split(const float* __restrict__ x, const float* __restrict__ y) {
    size_t i = (size_t)blockIdx.x * blockDim.x + threadIdx.x;   // over N*D/4
    float4 vx = ((const float4*)x)[i];
    float4 vy = ((const float4*)y)[i];
    size_t b = i * 4;
    const float* px = &vx.x;
    const float* py = &vy.x;
#pragma unroll
    for (int j = 0; j < 4; j++) {
        __nv_bfloat16 h = __float2bfloat16(px[j]);
        g_xh[b + j] = h;
        g_xl[b + j] = __float2bfloat16(px[j] - __bfloat162float(h));
        __nv_bfloat16 g = __float2bfloat16(py[j]);
        g_yh[b + j] = g;
        g_yl[b + j] = __float2bfloat16(py[j] - __bfloat162float(g));
    }
}

// ---------------- kernel 1: pos_sim ----------------
__global__ void k_pos(const float* __restrict__ x, const float* __restrict__ y) {
    int row = blockIdx.x * 8 + (threadIdx.x >> 5);
    int lane = threadIdx.x & 31;
    const float4* xr = (const float4*)(x + (size_t)row * DDIM);
    const float4* yr = (const float4*)(y + (size_t)row * DDIM);
    float s = 0.f;
#pragma unroll
    for (int i = lane; i < DDIM / 4; i += 32) {
        float4 a = xr[i], b = yr[i];
        s += a.x * b.x + a.y * b.y + a.z * b.z + a.w * b.w;
    }
#pragma unroll
    for (int o = 16; o; o >>= 1) s += __shfl_xor_sync(0xffffffffu, s, o);
    if (lane == 0) g_pos[row] = s;
}

// ---------------- kernel 2: HMMA bf16-split GEMM + fused masked argmax ----------------
__global__ __launch_bounds__(256)
void k_gemm_mma() {
    __shared__ __align__(128) __nv_bfloat16 As[2][BM * LDS_PAD];
    __shared__ __align__(128) __nv_bfloat16 Bs[2][BN * LDS_PAD];
    __shared__ float s_bv[2][BM];
    __shared__ int   s_bi[2][BM];

    const int tid  = threadIdx.x;
    const int wid  = tid >> 5;
    const int lane = tid & 31;
    const int wm   = wid & 3;        // 4 warps along M (32 rows each)
    const int wn   = wid >> 2;       // 2 warps along N (64 cols each)
    const int row0 = blockIdx.x * BM;
    const int col0 = blockIdx.y * BN;

    const __nv_bfloat16* Asrc[3] = { g_xh, g_xh, g_xl };
    const __nv_bfloat16* Bsrc[3] = { g_yh, g_yl, g_yh };

    float acc[2][8][4];
#pragma unroll
    for (int mt = 0; mt < 2; mt++)
#pragma unroll
        for (int nt = 0; nt < 8; nt++)
#pragma unroll
            for (int j = 0; j < 4; j++) acc[mt][nt][j] = 0.f;

    // load-task decomposition: 512 16B-chunks per matrix per iter, 2 per thread
    const int lr = tid >> 2;         // row 0..63 base (two iters of +64)
    const int lc = tid & 3;          // chunk 0..3

    const uint32_t sAs[2] = { (uint32_t)__cvta_generic_to_shared(&As[0][0]),
                              (uint32_t)__cvta_generic_to_shared(&As[1][0]) };
    const uint32_t sBs[2] = { (uint32_t)__cvta_generic_to_shared(&Bs[0][0]),
                              (uint32_t)__cvta_generic_to_shared(&Bs[1][0]) };

    // prologue: load iter 0 into buf 0
    {
        const __nv_bfloat16* A = Asrc[0] + (size_t)row0 * DDIM;
        const __nv_bfloat16* B = Bsrc[0] + (size_t)col0 * DDIM;
#pragma unroll
        for (int i = 0; i < 2; i++) {
            int r = lr + i * 64;
            cp16(sAs[0] + (r * LDS_PAD + lc * 8) * 2, A + (size_t)r * DDIM + lc * 8);
            cp16(sBs[0] + (r * LDS_PAD + lc * 8) * 2, B + (size_t)r * DDIM + lc * 8);
        }
        cp_commit();
    }

    for (int it = 0; it < NITER; ++it) {
        const int p = it & 1;
        cp_wait0();
        __syncthreads();

        if (it + 1 < NITER) {
            const int term = (it + 1) >> 5;
            const int k0 = ((it + 1) & 31) * BK;
            const __nv_bfloat16* A = Asrc[term] + (size_t)row0 * DDIM + k0;
            const __nv_bfloat16* B = Bsrc[term] + (size_t)col0 * DDIM + k0;
#pragma unroll
            for (int i = 0; i < 2; i++) {
                int r = lr + i * 64;
                cp16(sAs[p ^ 1] + (r * LDS_PAD + lc * 8) * 2, A + (size_t)r * DDIM + lc * 8);
                cp16(sBs[p ^ 1] + (r * LDS_PAD + lc * 8) * 2, B + (size_t)r * DDIM + lc * 8);
            }
            cp_commit();
        }

        // compute on buffer p: 2 k-steps of 16
#pragma unroll
        for (int ks = 0; ks < 2; ks++) {
            uint32_t a[2][4];
#pragma unroll
            for (int mt = 0; mt < 2; mt++) {
                uint32_t addr = sAs[p] +
                    ((wm * 32 + mt * 16 + (lane & 15)) * LDS_PAD + ks * 16 + (lane >> 4) * 8) * 2;
                ldsm_x4(a[mt][0], a[mt][1], a[mt][2], a[mt][3], addr);
            }
            uint32_t b[8][2];
#pragma unroll
            for (int nt = 0; nt < 8; nt++) {
                uint32_t addr = sBs[p] +
                    ((wn * 64 + nt * 8 + (lane & 7)) * LDS_PAD + ks * 16 + ((lane >> 3) & 1) * 8) * 2;
                ldsm_x2(b[nt][0], b[nt][1], addr);
            }
#pragma unroll
            for (int mt = 0; mt < 2; mt++)
#pragma unroll
                for (int nt = 0; nt < 8; nt++)
                    mma_bf16(acc[mt][nt], a[mt][0], a[mt][1], a[mt][2], a[mt][3], b[nt][0], b[nt][1]);
        }
    }
    __syncthreads();

    // ---- epilogue: masked argmax ----
    // lane owns rows: wm*32 + mt*16 + lane/4 + rh*8; cols: col0 + wn*64 + nt*8 + 2*(lane%4) + j
#pragma unroll
    for (int mt = 0; mt < 2; mt++) {
#pragma unroll
        for (int rh = 0; rh < 2; rh++) {
            const int rloc = wm * 32 + mt * 16 + (lane >> 2) + rh * 8;
            const int row  = row0 + rloc;
            const float pos = g_pos[row];
            float bv = NEG_INF;
            int bi = 0x7fffffff;
#pragma unroll
            for (int nt = 0; nt < 8; nt++) {
#pragma unroll
                for (int j = 0; j < 2; j++) {
                    int col = col0 + wn * 64 + nt * 8 + 2 * (lane & 3) + j;
                    float s = acc[mt][nt][rh * 2 + j];
                    float v = (col == row || s > pos) ? -1.0f : s;
                    if (v > bv || (v == bv && col < bi)) { bv = v; bi = col; }
                }
            }
            // reduce across the 4 lanes of the quad sharing this row
#pragma unroll
            for (int o = 1; o < 4; o <<= 1) {
                float ov = __shfl_xor_sync(0xffffffffu, bv, o);
                int   oi = __shfl_xor_sync(0xffffffffu, bi, o);
                if (ov > bv || (ov == bv && oi < bi)) { bv = ov; bi = oi; }
            }
            if ((lane & 3) == 0) { s_bv[wn][rloc] = bv; s_bi[wn][rloc] = bi; }
        }
    }
    __syncthreads();

    if (tid < BM) {
        float bv = s_bv[0][tid]; int bi = s_bi[0][tid];
        float v1 = s_bv[1][tid]; int i1 = s_bi[1][tid];
        if (v1 > bv || (v1 == bv && i1 < bi)) { bv = v1; bi = i1; }
        g_pval[(size_t)blockIdx.y * NROWS + row0 + tid] = bv;
        g_pidx[(size_t)blockIdx.y * NROWS + row0 + tid] = bi;
    }
}

// ---------------- kernel 3: merge splits, exact gather dot, loss term ----------------
__global__ void k_neg(const float* __restrict__ x, const float* __restrict__ y) {
    int row = blockIdx.x * 8 + (threadIdx.x >> 5);
    int lane = threadIdx.x & 31;

    float bv = NEG_INF;
    int bi = 0x7fffffff;
#pragma unroll 8
    for (int s = 0; s < NTILE_N; s++) {   // ascending col tiles preserve first-index ties
        float v = g_pval[(size_t)s * NROWS + row];
        int i = g_pidx[(size_t)s * NROWS + row];
        if (v > bv || (v == bv && i < bi)) { bv = v; bi = i; }
    }

    const float4* xr = (const float4*)(x + (size_t)row * DDIM);
    const float4* yr = (const float4*)(y + (size_t)bi * DDIM);
    float s = 0.f;
#pragma unroll
    for (int i = lane; i < DDIM / 4; i += 32) {
        float4 a = xr[i], b = yr[i];
        s += a.x * b.x + a.y * b.y + a.z * b.z + a.w * b.w;
    }
#pragma unroll
    for (int o = 16; o; o >>= 1) s += __shfl_xor_sync(0xffffffffu, s, o);
    if (lane == 0) g_terms[row] = fmaxf(0.f, MARGIN_F - g_pos[row] + s);
}

// ---------------- kernel 4: deterministic mean ----------------
__global__ void k_reduce(float* __restrict__ out) {
    __shared__ float sm[1024];
    int tid = threadIdx.x;
    float s = 0.f;
#pragma unroll
    for (int i = 0; i < NROWS / 1024; i++) s += g_terms[tid + i * 1024];
    sm[tid] = s;
    __syncthreads();
    for (int o = 512; o; o >>= 1) {
        if (tid < o) sm[tid] += sm[tid + o];
        __syncthreads();
    }
    if (tid == 0) out[0] = sm[0] / (float)NROWS;
}

// ---------------- launch ----------------
extern "C" void kernel_launch(void* const* d_in, const int* in_sizes, int n_in,
                              void* d_out, int out_size) {
    const float* x = (const float*)d_in[0];
    const float* y = (const float*)d_in[1];
    float* out = (float*)d_out;

    k_split<<<(NROWS * DDIM / 4) / 256, 256>>>(x, y);
    k_pos<<<NROWS / 8, 256>>>(x, y);
    dim3 grid(NROWS / BM, NROWS / BN);
    k_gemm_mma<<<grid, 256>>>();
    k_neg<<<NROWS / 8, 256>>>(x, y);
    k_reduce<<<1, 1024>>>(out);
}

// round 6
// speedup vs baseline: 4.3795x; 1.7649x over previous
#include <cuda_runtime.h>
#include <cuda_fp16.h>
#include <cstdint>

#define NROWS 8192
#define DDIM  1024
#define MARGIN_F 0.05f
#define NEG_INF (__int_as_float(0xff800000))

#define BM 128
#define BN 128
#define BK 32
#define NITER (DDIM / BK)            // 32
#define NTILE_N (NROWS / BN)         // 64
#define LDS_PAD 40                   // halves per smem row (32 + 8 pad)

// ---------------- device scratch ----------------
__device__ __half g_xh[(size_t)NROWS * DDIM];
__device__ __half g_yh[(size_t)NROWS * DDIM];
__device__ float g_pos[NROWS];
__device__ float g_pval[(size_t)NTILE_N * NROWS];
__device__ int   g_pidx[(size_t)NTILE_N * NROWS];
__device__ float g_terms[NROWS];

// ---------------- asm helpers ----------------
__device__ __forceinline__ void cp16(uint32_t sdst, const void* gsrc) {
    asm volatile("cp.async.cg.shared.global [%0], [%1], 16;" :: "r"(sdst), "l"(gsrc) : "memory");
}
__device__ __forceinline__ void cp_commit() { asm volatile("cp.async.commit_group;" ::: "memory"); }
__device__ __forceinline__ void cp_wait0()  { asm volatile("cp.async.wait_group 0;" ::: "memory"); }

__device__ __forceinline__ void ldsm_x4(uint32_t& a0, uint32_t& a1, uint32_t& a2, uint32_t& a3, uint32_t addr) {
    asm volatile("ldmatrix.sync.aligned.m8n8.x4.shared.b16 {%0,%1,%2,%3}, [%4];"
        : "=r"(a0), "=r"(a1), "=r"(a2), "=r"(a3) : "r"(addr));
}
__device__ __forceinline__ void ldsm_x2(uint32_t& b0, uint32_t& b1, uint32_t addr) {
    asm volatile("ldmatrix.sync.aligned.m8n8.x2.shared.b16 {%0,%1}, [%2];"
        : "=r"(b0), "=r"(b1) : "r"(addr));
}
__device__ __forceinline__ void mma_f16(float* c, uint32_t a0, uint32_t a1, uint32_t a2, uint32_t a3,
                                        uint32_t b0, uint32_t b1) {
    asm volatile("mma.sync.aligned.m16n8k16.row.col.f32.f16.f16.f32 "
        "{%0,%1,%2,%3}, {%4,%5,%6,%7}, {%8,%9}, {%0,%1,%2,%3};"
        : "+f"(c[0]), "+f"(c[1]), "+f"(c[2]), "+f"(c[3])
        : "r"(a0), "r"(a1), "r"(a2), "r"(a3), "r"(b0), "r"(b1));
}

// ---------------- kernel 0: fp32 -> fp16 ----------------
__global__ void k_half(const float* __restrict__ x, const float* __restrict__ y) {
    size_t i = (size_t)blockIdx.x * blockDim.x + threadIdx.x;   // over N*D/4
    float4 vx = ((const float4*)x)[i];
    float4 vy = ((const float4*)y)[i];
    ((__half2*)g_xh)[i * 2]     = __floats2half2_rn(vx.x, vx.y);
    ((__half2*)g_xh)[i * 2 + 1] = __floats2half2_rn(vx.z, vx.w);
    ((__half2*)g_yh)[i * 2]     = __floats2half2_rn(vy.x, vy.y);
    ((__half2*)g_yh)[i * 2 + 1] = __floats2half2_rn(vy.z, vy.w);
}

// ---------------- kernel 1: pos_sim (exact fp32) ----------------
__global__ void k_pos(const float* __restrict__ x, const float* __restrict__ y) {
    int row = blockIdx.x * 8 + (threadIdx.x >> 5);
    int lane = threadIdx.x & 31;
    const float4* xr = (const float4*)(x + (size_t)row * DDIM);
    const float4* yr = (const float4*)(y + (size_t)row * DDIM);
    float s = 0.f;
#pragma unroll
    for (int i = lane; i < DDIM / 4; i += 32) {
        float4 a = xr[i], b = yr[i];
        s += a.x * b.x + a.y * b.y + a.z * b.z + a.w * b.w;
    }
#pragma unroll
    for (int o = 16; o; o >>= 1) s += __shfl_xor_sync(0xffffffffu, s, o);
    if (lane == 0) g_pos[row] = s;
}

// ---------------- kernel 2: fp16 HMMA GEMM + fused masked argmax ----------------
// Static smem, 2-stage double buffer (proven R3 skeleton), single fp16 pass.
__global__ __launch_bounds__(256)
void k_gemm_mma() {
    __shared__ __align__(128) __half As[2][BM * LDS_PAD];
    __shared__ __align__(128) __half Bs[2][BN * LDS_PAD];
    __shared__ float s_bv[2][BM];
    __shared__ int   s_bi[2][BM];

    const int tid  = threadIdx.x;
    const int wid  = tid >> 5;
    const int lane = tid & 31;
    const int wm   = wid & 3;        // 4 warps along M (32 rows each)
    const int wn   = wid >> 2;       // 2 warps along N (64 cols each)
    const int row0 = blockIdx.x * BM;
    const int col0 = blockIdx.y * BN;

    float acc[2][8][4];
#pragma unroll
    for (int mt = 0; mt < 2; mt++)
#pragma unroll
        for (int nt = 0; nt < 8; nt++)
#pragma unroll
            for (int j = 0; j < 4; j++) acc[mt][nt][j] = 0.f;

    const int lr = tid >> 2;         // row base 0..63 (two iters of +64)
    const int lc = tid & 3;          // 16B chunk 0..3

    const uint32_t sAs[2] = { (uint32_t)__cvta_generic_to_shared(&As[0][0]),
                              (uint32_t)__cvta_generic_to_shared(&As[1][0]) };
    const uint32_t sBs[2] = { (uint32_t)__cvta_generic_to_shared(&Bs[0][0]),
                              (uint32_t)__cvta_generic_to_shared(&Bs[1][0]) };

    // prologue: load iter 0 into buf 0
    {
        const __half* A = g_xh + (size_t)row0 * DDIM;
        const __half* B = g_yh + (size_t)col0 * DDIM;
#pragma unroll
        for (int i = 0; i < 2; i++) {
            int r = lr + i * 64;
            cp16(sAs[0] + (r * LDS_PAD + lc * 8) * 2, A + (size_t)r * DDIM + lc * 8);
            cp16(sBs[0] + (r * LDS_PAD + lc * 8) * 2, B + (size_t)r * DDIM + lc * 8);
        }
        cp_commit();
    }

    for (int it = 0; it < NITER; ++it) {
        const int p = it & 1;
        cp_wait0();
        __syncthreads();

        if (it + 1 < NITER) {
            const int k0 = (it + 1) * BK;
            const __half* A = g_xh + (size_t)row0 * DDIM + k0;
            const __half* B = g_yh + (size_t)col0 * DDIM + k0;
#pragma unroll
            for (int i = 0; i < 2; i++) {
                int r = lr + i * 64;
                cp16(sAs[p ^ 1] + (r * LDS_PAD + lc * 8) * 2, A + (size_t)r * DDIM + lc * 8);
                cp16(sBs[p ^ 1] + (r * LDS_PAD + lc * 8) * 2, B + (size_t)r * DDIM + lc * 8);
            }
            cp_commit();
        }

        // compute on buffer p: 2 k-steps of 16
#pragma unroll
        for (int ks = 0; ks < 2; ks++) {
            uint32_t a[2][4];
#pragma unroll
            for (int mt = 0; mt < 2; mt++) {
                uint32_t addr = sAs[p] +
                    ((wm * 32 + mt * 16 + (lane & 15)) * LDS_PAD + ks * 16 + (lane >> 4) * 8) * 2;
                ldsm_x4(a[mt][0], a[mt][1], a[mt][2], a[mt][3], addr);
            }
            uint32_t b[8][2];
#pragma unroll
            for (int nt = 0; nt < 8; nt++) {
                uint32_t addr = sBs[p] +
                    ((wn * 64 + nt * 8 + (lane & 7)) * LDS_PAD + ks * 16 + ((lane >> 3) & 1) * 8) * 2;
                ldsm_x2(b[nt][0], b[nt][1], addr);
            }
#pragma unroll
            for (int mt = 0; mt < 2; mt++)
#pragma unroll
                for (int nt = 0; nt < 8; nt++)
                    mma_f16(acc[mt][nt], a[mt][0], a[mt][1], a[mt][2], a[mt][3], b[nt][0], b[nt][1]);
        }
    }
    __syncthreads();

    // ---- epilogue: masked argmax ----
#pragma unroll
    for (int mt = 0; mt < 2; mt++) {
#pragma unroll
        for (int rh = 0; rh < 2; rh++) {
            const int rloc = wm * 32 + mt * 16 + (lane >> 2) + rh * 8;
            const int row  = row0 + rloc;
            const float pos = g_pos[row];
            float bv = NEG_INF;
            int bi = 0x7fffffff;
#pragma unroll
            for (int nt = 0; nt < 8; nt++) {
#pragma unroll
                for (int j = 0; j < 2; j++) {
                    int col = col0 + wn * 64 + nt * 8 + 2 * (lane & 3) + j;
                    float s = acc[mt][nt][rh * 2 + j];
                    float v = (col == row || s > pos) ? -1.0f : s;
                    if (v > bv || (v == bv && col < bi)) { bv = v; bi = col; }
                }
            }
#pragma unroll
            for (int o = 1; o < 4; o <<= 1) {
                float ov = __shfl_xor_sync(0xffffffffu, bv, o);
                int   oi = __shfl_xor_sync(0xffffffffu, bi, o);
                if (ov > bv || (ov == bv && oi < bi)) { bv = ov; bi = oi; }
            }
            if ((lane & 3) == 0) { s_bv[wn][rloc] = bv; s_bi[wn][rloc] = bi; }
        }
    }
    __syncthreads();

    if (tid < BM) {
        float bv = s_bv[0][tid]; int bi = s_bi[0][tid];
        float v1 = s_bv[1][tid]; int i1 = s_bi[1][tid];
        if (v1 > bv || (v1 == bv && i1 < bi)) { bv = v1; bi = i1; }
        g_pval[(size_t)blockIdx.y * NROWS + row0 + tid] = bv;
        g_pidx[(size_t)blockIdx.y * NROWS + row0 + tid] = bi;
    }
}

// ---------------- kernel 3: merge splits, exact gather dot, loss term ----------------
__global__ void k_neg(const float* __restrict__ x, const float* __restrict__ y) {
    int row = blockIdx.x * 8 + (threadIdx.x >> 5);
    int lane = threadIdx.x & 31;

    float bv = NEG_INF;
    int bi = 0x7fffffff;
#pragma unroll 8
    for (int s = 0; s < NTILE_N; s++) {   // ascending col tiles preserve first-index ties
        float v = g_pval[(size_t)s * NROWS + row];
        int i = g_pidx[(size_t)s * NROWS + row];
        if (v > bv || (v == bv && i < bi)) { bv = v; bi = i; }
    }

    const float4* xr = (const float4*)(x + (size_t)row * DDIM);
    const float4* yr = (const float4*)(y + (size_t)bi * DDIM);
    float s = 0.f;
#pragma unroll
    for (int i = lane; i < DDIM / 4; i += 32) {
        float4 a = xr[i], b = yr[i];
        s += a.x * b.x + a.y * b.y + a.z * b.z + a.w * b.w;
    }
#pragma unroll
    for (int o = 16; o; o >>= 1) s += __shfl_xor_sync(0xffffffffu, s, o);
    if (lane == 0) g_terms[row] = fmaxf(0.f, MARGIN_F - g_pos[row] + s);
}

// ---------------- kernel 4: deterministic mean ----------------
__global__ void k_reduce(float* __restrict__ out) {
    __shared__ float sm[1024];
    int tid = threadIdx.x;
    float s = 0.f;
#pragma unroll
    for (int i = 0; i < NROWS / 1024; i++) s += g_terms[tid + i * 1024];
    sm[tid] = s;
    __syncthreads();
    for (int o = 512; o; o >>= 1) {
        if (tid < o) sm[tid] += sm[tid + o];
        __syncthreads();
    }
    if (tid == 0) out[0] = sm[0] / (float)NROWS;
}

// ---------------- launch (kernel launches ONLY; no runtime attribute calls) ----------------
extern "C" void kernel_launch(void* const* d_in, const int* in_sizes, int n_in,
                              void* d_out, int out_size) {
    const float* x = (const float*)d_in[0];
    const float* y = (const float*)d_in[1];
    float* out = (float*)d_out;

    k_half<<<(NROWS * DDIM / 4) / 256, 256>>>(x, y);
    k_pos<<<NROWS / 8, 256>>>(x, y);
    dim3 grid(NROWS / BM, NROWS / BN);
    k_gemm_mma<<<grid, 256>>>();
    k_neg<<<NROWS / 8, 256>>>(x, y);
    k_reduce<<<1, 1024>>>(out);
}

// round 7
// speedup vs baseline: 4.4843x; 1.0239x over previous
#include <cuda_runtime.h>
#include <cuda_fp16.h>
#include <cstdint>

#define NROWS 8192
#define DDIM  1024
#define MARGIN_F 0.05f
#define NEG_INF (__int_as_float(0xff800000))

#define BM 128
#define BN 256
#define BK 32
#define NITER (DDIM / BK)            // 32
#define NTILE_N (NROWS / BN)         // 32

// smem: 64B rows (32 halves), XOR chunk swizzle, no pad
#define A_HALVES (BM * BK)           // 4096 -> 8KB per stage
#define B_HALVES (BN * BK)           // 8192 -> 16KB per stage

// ---------------- device scratch ----------------
__device__ __half g_xh[(size_t)NROWS * DDIM];
__device__ __half g_yh[(size_t)NROWS * DDIM];
__device__ float g_pos[NROWS];
__device__ float g_pval[(size_t)NTILE_N * NROWS];
__device__ int   g_pidx[(size_t)NTILE_N * NROWS];
__device__ float g_terms[NROWS];

// ---------------- asm helpers ----------------
__device__ __forceinline__ void cp16(uint32_t sdst, const void* gsrc) {
    asm volatile("cp.async.cg.shared.global [%0], [%1], 16;" :: "r"(sdst), "l"(gsrc) : "memory");
}
__device__ __forceinline__ void cp_commit() { asm volatile("cp.async.commit_group;" ::: "memory"); }
__device__ __forceinline__ void cp_wait0()  { asm volatile("cp.async.wait_group 0;" ::: "memory"); }

__device__ __forceinline__ void ldsm_x4(uint32_t& a0, uint32_t& a1, uint32_t& a2, uint32_t& a3, uint32_t addr) {
    asm volatile("ldmatrix.sync.aligned.m8n8.x4.shared.b16 {%0,%1,%2,%3}, [%4];"
        : "=r"(a0), "=r"(a1), "=r"(a2), "=r"(a3) : "r"(addr));
}
__device__ __forceinline__ void mma_f16(float* c, uint32_t a0, uint32_t a1, uint32_t a2, uint32_t a3,
                                        uint32_t b0, uint32_t b1) {
    asm volatile("mma.sync.aligned.m16n8k16.row.col.f32.f16.f16.f32 "
        "{%0,%1,%2,%3}, {%4,%5,%6,%7}, {%8,%9}, {%0,%1,%2,%3};"
        : "+f"(c[0]), "+f"(c[1]), "+f"(c[2]), "+f"(c[3])
        : "r"(a0), "r"(a1), "r"(a2), "r"(a3), "r"(b0), "r"(b1));
}

// swizzled byte offset within a tile: row has 4 16B chunks; c' = c ^ ((row>>1)&3)
__device__ __forceinline__ uint32_t sw_off(int row, int chunk) {
    return (uint32_t)(row * 64 + ((chunk ^ ((row >> 1) & 3)) << 4));
}

// ---------------- kernel 0: fp32 -> fp16 ----------------
__global__ void k_half(const float* __restrict__ x, const float* __restrict__ y) {
    size_t i = (size_t)blockIdx.x * blockDim.x + threadIdx.x;   // over N*D/4
    float4 vx = ((const float4*)x)[i];
    float4 vy = ((const float4*)y)[i];
    ((__half2*)g_xh)[i * 2]     = __floats2half2_rn(vx.x, vx.y);
    ((__half2*)g_xh)[i * 2 + 1] = __floats2half2_rn(vx.z, vx.w);
    ((__half2*)g_yh)[i * 2]     = __floats2half2_rn(vy.x, vy.y);
    ((__half2*)g_yh)[i * 2 + 1] = __floats2half2_rn(vy.z, vy.w);
}

// ---------------- kernel 1: pos_sim (exact fp32) ----------------
__global__ void k_pos(const float* __restrict__ x, const float* __restrict__ y) {
    int row = blockIdx.x * 8 + (threadIdx.x >> 5);
    int lane = threadIdx.x & 31;
    const float4* xr = (const float4*)(x + (size_t)row * DDIM);
    const float4* yr = (const float4*)(y + (size_t)row * DDIM);
    float s = 0.f;
#pragma unroll
    for (int i = lane; i < DDIM / 4; i += 32) {
        float4 a = xr[i], b = yr[i];
        s += a.x * b.x + a.y * b.y + a.z * b.z + a.w * b.w;
    }
#pragma unroll
    for (int o = 16; o; o >>= 1) s += __shfl_xor_sync(0xffffffffu, s, o);
    if (lane == 0) g_pos[row] = s;
}

// ---------------- kernel 2: fp16 HMMA 128x256 GEMM + fused masked argmax ----------------
__global__ __launch_bounds__(256)
void k_gemm_mma() {
    __shared__ __align__(128) __half As[2][A_HALVES];   // 16 KB
    __shared__ __align__(128) __half Bs[2][B_HALVES];   // 32 KB  (total = 48 KB exactly)

    const int tid  = threadIdx.x;
    const int wid  = tid >> 5;
    const int lane = tid & 31;
    const int wm   = wid >> 2;       // 0..1: 64 rows each
    const int wn   = wid & 3;        // 0..3: 64 cols each
    const int row0 = blockIdx.x * BM;
    const int col0 = blockIdx.y * BN;

    float acc[4][8][4];
#pragma unroll
    for (int mt = 0; mt < 4; mt++)
#pragma unroll
        for (int nt = 0; nt < 8; nt++)
#pragma unroll
            for (int j = 0; j < 4; j++) acc[mt][nt][j] = 0.f;

    const int lr = tid >> 2;         // row base 0..63
    const int lc = tid & 3;          // chunk 0..3

    const uint32_t sAs[2] = { (uint32_t)__cvta_generic_to_shared(&As[0][0]),
                              (uint32_t)__cvta_generic_to_shared(&As[1][0]) };
    const uint32_t sBs[2] = { (uint32_t)__cvta_generic_to_shared(&Bs[0][0]),
                              (uint32_t)__cvta_generic_to_shared(&Bs[1][0]) };

    auto load_stage = [&](int s, int k0) {
        const __half* A = g_xh + (size_t)row0 * DDIM + k0;
        const __half* B = g_yh + (size_t)col0 * DDIM + k0;
#pragma unroll
        for (int i = 0; i < 2; i++) {
            int r = lr + i * 64;
            cp16(sAs[s] + sw_off(r, lc), A + (size_t)r * DDIM + lc * 8);
        }
#pragma unroll
        for (int i = 0; i < 4; i++) {
            int r = lr + i * 64;
            cp16(sBs[s] + sw_off(r, lc), B + (size_t)r * DDIM + lc * 8);
        }
    };

    load_stage(0, 0);
    cp_commit();

    for (int it = 0; it < NITER; ++it) {
        const int p = it & 1;
        cp_wait0();
        __syncthreads();

        if (it + 1 < NITER) load_stage(p ^ 1, (it + 1) * BK);
        cp_commit();

#pragma unroll
        for (int ks = 0; ks < 2; ks++) {
            // A frags: 4 m16 tiles
            uint32_t a[4][4];
#pragma unroll
            for (int mt = 0; mt < 4; mt++) {
                int r = wm * 64 + mt * 16 + (lane & 15);
                uint32_t addr = sAs[p] + sw_off(r, ks * 2 + (lane >> 4));
                ldsm_x4(a[mt][0], a[mt][1], a[mt][2], a[mt][3], addr);
            }
            // B frags: 4 n16 tiles -> 8 n8 frags
            uint32_t b[8][2];
#pragma unroll
            for (int np = 0; np < 4; np++) {
                int r = wn * 64 + np * 16 + (lane & 15);
                uint32_t addr = sBs[p] + sw_off(r, ks * 2 + (lane >> 4));
                uint32_t r0, r1, r2, r3;
                ldsm_x4(r0, r1, r2, r3, addr);
                b[np * 2][0] = r0;     b[np * 2][1] = r2;      // rows n0-7
                b[np * 2 + 1][0] = r1; b[np * 2 + 1][1] = r3;  // rows n8-15
            }
#pragma unroll
            for (int mt = 0; mt < 4; mt++)
#pragma unroll
                for (int nt = 0; nt < 8; nt++)
                    mma_f16(acc[mt][nt], a[mt][0], a[mt][1], a[mt][2], a[mt][3], b[nt][0], b[nt][1]);
        }
    }
    __syncthreads();

    // ---- epilogue: masked argmax; merge arrays reuse the A buffer ----
    float* s_bv = (float*)&As[0][0];            // [4][128]
    int*   s_bi = (int*)((char*)&As[0][0] + 4 * BM * sizeof(float));

#pragma unroll
    for (int mt = 0; mt < 4; mt++) {
#pragma unroll
        for (int rh = 0; rh < 2; rh++) {
            const int rloc = wm * 64 + mt * 16 + (lane >> 2) + rh * 8;
            const int row  = row0 + rloc;
            const float pos = g_pos[row];
            float bv = NEG_INF;
            int bi = 0x7fffffff;
#pragma unroll
            for (int nt = 0; nt < 8; nt++) {
#pragma unroll
                for (int j = 0; j < 2; j++) {
                    int col = col0 + wn * 64 + nt * 8 + 2 * (lane & 3) + j;
                    float s = acc[mt][nt][rh * 2 + j];
                    float v = (col == row || s > pos) ? -1.0f : s;
                    if (v > bv || (v == bv && col < bi)) { bv = v; bi = col; }
                }
            }
#pragma unroll
            for (int o = 1; o < 4; o <<= 1) {
                float ov = __shfl_xor_sync(0xffffffffu, bv, o);
                int   oi = __shfl_xor_sync(0xffffffffu, bi, o);
                if (ov > bv || (ov == bv && oi < bi)) { bv = ov; bi = oi; }
            }
            if ((lane & 3) == 0) { s_bv[wn * BM + rloc] = bv; s_bi[wn * BM + rloc] = bi; }
        }
    }
    __syncthreads();

    if (tid < BM) {
        float bv = s_bv[tid]; int bi = s_bi[tid];
#pragma unroll
        for (int w = 1; w < 4; w++) {            // ascending col order: first-index ties
            float v = s_bv[w * BM + tid]; int i = s_bi[w * BM + tid];
            if (v > bv || (v == bv && i < bi)) { bv = v; bi = i; }
        }
        g_pval[(size_t)blockIdx.y * NROWS + row0 + tid] = bv;
        g_pidx[(size_t)blockIdx.y * NROWS + row0 + tid] = bi;
    }
}

// ---------------- kernel 3: merge splits, exact gather dot, loss term ----------------
__global__ void k_neg(const float* __restrict__ x, const float* __restrict__ y) {
    int row = blockIdx.x * 8 + (threadIdx.x >> 5);
    int lane = threadIdx.x & 31;

    float bv = NEG_INF;
    int bi = 0x7fffffff;
#pragma unroll 8
    for (int s = 0; s < NTILE_N; s++) {   // ascending col tiles preserve first-index ties
        float v = g_pval[(size_t)s * NROWS + row];
        int i = g_pidx[(size_t)s * NROWS + row];
        if (v > bv || (v == bv && i < bi)) { bv = v; bi = i; }
    }

    const float4* xr = (const float4*)(x + (size_t)row * DDIM);
    const float4* yr = (const float4*)(y + (size_t)bi * DDIM);
    float s = 0.f;
#pragma unroll
    for (int i = lane; i < DDIM / 4; i += 32) {
        float4 a = xr[i], b = yr[i];
        s += a.x * b.x + a.y * b.y + a.z * b.z + a.w * b.w;
    }
#pragma unroll
    for (int o = 16; o; o >>= 1) s += __shfl_xor_sync(0xffffffffu, s, o);
    if (lane == 0) g_terms[row] = fmaxf(0.f, MARGIN_F - g_pos[row] + s);
}

// ---------------- kernel 4: deterministic mean ----------------
__global__ void k_reduce(float* __restrict__ out) {
    __shared__ float sm[1024];
    int tid = threadIdx.x;
    float s = 0.f;
#pragma unroll
    for (int i = 0; i < NROWS / 1024; i++) s += g_terms[tid + i * 1024];
    sm[tid] = s;
    __syncthreads();
    for (int o = 512; o; o >>= 1) {
        if (tid < o) sm[tid] += sm[tid + o];
        __syncthreads();
    }
    if (tid == 0) out[0] = sm[0] / (float)NROWS;
}

// ---------------- launch (kernel launches ONLY) ----------------
extern "C" void kernel_launch(void* const* d_in, const int* in_sizes, int n_in,
                              void* d_out, int out_size) {
    const float* x = (const float*)d_in[0];
    const float* y = (const float*)d_in[1];
    float* out = (float*)d_out;

    k_half<<<(NROWS * DDIM / 4) / 256, 256>>>(x, y);
    k_pos<<<NROWS / 8, 256>>>(x, y);
    dim3 grid(NROWS / BM, NROWS / BN);
    k_gemm_mma<<<grid, 256>>>();
    k_neg<<<NROWS / 8, 256>>>(x, y);
    k_reduce<<<1, 1024>>>(out);
}

// round 9
// speedup vs baseline: 7.3787x; 1.6455x over previous
#include <cuda_runtime.h>
#include <cuda_fp16.h>
#include <cstdint>

#define NROWS 8192
#define DDIM  1024
#define MARGIN_F 0.05f
#define NEG_INF (__int_as_float(0xff800000))

#define BM 128
#define BN 128
#define BK 16                         // halves per stage -> 32B rows, 2 chunks
#define NITER (DDIM / BK)             // 64
#define NSTAGE 3
#define NTILE_N (NROWS / BN)          // 64
#define STG_HALVES (BM * BK)          // 2048 halves = 4KB per matrix per stage

// ---------------- device scratch ----------------
__device__ __half g_xh[(size_t)NROWS * DDIM];
__device__ __half g_yh[(size_t)NROWS * DDIM];
__device__ float g_pos[NROWS];
__device__ float g_pval[(size_t)NTILE_N * NROWS];
__device__ int   g_pidx[(size_t)NTILE_N * NROWS];
__device__ float g_terms[NROWS];

// ---------------- asm helpers ----------------
__device__ __forceinline__ void cp16(uint32_t sdst, const void* gsrc) {
    asm volatile("cp.async.cg.shared.global [%0], [%1], 16;" :: "r"(sdst), "l"(gsrc) : "memory");
}
__device__ __forceinline__ void cp_commit() { asm volatile("cp.async.commit_group;" ::: "memory"); }
__device__ __forceinline__ void cp_wait1()  { asm volatile("cp.async.wait_group 1;" ::: "memory"); }
__device__ __forceinline__ void cp_wait0()  { asm volatile("cp.async.wait_group 0;" ::: "memory"); }

__device__ __forceinline__ void ldsm_x4(uint32_t& a0, uint32_t& a1, uint32_t& a2, uint32_t& a3, uint32_t addr) {
    asm volatile("ldmatrix.sync.aligned.m8n8.x4.shared.b16 {%0,%1,%2,%3}, [%4];"
        : "=r"(a0), "=r"(a1), "=r"(a2), "=r"(a3) : "r"(addr));
}
__device__ __forceinline__ void mma_f16(float* c, uint32_t a0, uint32_t a1, uint32_t a2, uint32_t a3,
                                        uint32_t b0, uint32_t b1) {
    asm volatile("mma.sync.aligned.m16n8k16.row.col.f32.f16.f16.f32 "
        "{%0,%1,%2,%3}, {%4,%5,%6,%7}, {%8,%9}, {%0,%1,%2,%3};"
        : "+f"(c[0]), "+f"(c[1]), "+f"(c[2]), "+f"(c[3])
        : "r"(a0), "r"(a1), "r"(a2), "r"(a3), "r"(b0), "r"(b1));
}

// 32B rows, 2 x 16B chunks; swizzle: c' = c ^ ((row>>2)&1)
// ldsm phase: 8 consecutive rows, same logical chunk -> rows 0-3 slot c, rows 4-7 slot c^1:
// 8 distinct 16B slots tiling one 128B phase -> conflict-free.
__device__ __forceinline__ uint32_t sw16(int row, int chunk) {
    return (uint32_t)(row * 32 + ((chunk ^ ((row >> 2) & 1)) << 4));
}

// ---------------- kernel 0: fused fp16 convert + exact pos_sim ----------------
__global__ void k_prep(const float* __restrict__ x, const float* __restrict__ y) {
    int row = blockIdx.x * 8 + (threadIdx.x >> 5);
    int lane = threadIdx.x & 31;
    const float4* xr = (const float4*)(x + (size_t)row * DDIM);
    const float4* yr = (const float4*)(y + (size_t)row * DDIM);
    __half2* xo = ((__half2*)g_xh) + (size_t)row * (DDIM / 2);
    __half2* yo = ((__half2*)g_yh) + (size_t)row * (DDIM / 2);
    float s = 0.f;
#pragma unroll
    for (int i = 0; i < 8; i++) {
        int j = lane + i * 32;
        float4 a = xr[j], b = yr[j];
        s += a.x * b.x + a.y * b.y + a.z * b.z + a.w * b.w;
        xo[j * 2]     = __floats2half2_rn(a.x, a.y);
        xo[j * 2 + 1] = __floats2half2_rn(a.z, a.w);
        yo[j * 2]     = __floats2half2_rn(b.x, b.y);
        yo[j * 2 + 1] = __floats2half2_rn(b.z, b.w);
    }
#pragma unroll
    for (int o = 16; o; o >>= 1) s += __shfl_xor_sync(0xffffffffu, s, o);
    if (lane == 0) g_pos[row] = s;
}

// ---------------- kernel 1: fp16 HMMA GEMM (2 CTAs/SM) + fused masked argmax ----------------
__global__ __launch_bounds__(256, 2)
void k_gemm_mma() {
    __shared__ __align__(128) __half As[NSTAGE][STG_HALVES];   // 12 KB
    __shared__ __align__(128) __half Bs[NSTAGE][STG_HALVES];   // 12 KB (24 KB/CTA)

    const int tid  = threadIdx.x;
    const int wid  = tid >> 5;
    const int lane = tid & 31;
    const int wm   = wid & 3;        // 4 warps along M (32 rows each)
    const int wn   = wid >> 2;       // 2 warps along N (64 cols each)
    const int row0 = blockIdx.x * BM;
    const int col0 = blockIdx.y * BN;

    float acc[2][8][4];
#pragma unroll
    for (int mt = 0; mt < 2; mt++)
#pragma unroll
        for (int nt = 0; nt < 8; nt++)
#pragma unroll
            for (int j = 0; j < 4; j++) acc[mt][nt][j] = 0.f;

    const int lr = tid >> 1;         // row 0..127
    const int lc = tid & 1;          // chunk 0..1

    uint32_t sA[NSTAGE], sB[NSTAGE];
#pragma unroll
    for (int s = 0; s < NSTAGE; s++) {
        sA[s] = (uint32_t)__cvta_generic_to_shared(&As[s][0]);
        sB[s] = (uint32_t)__cvta_generic_to_shared(&Bs[s][0]);
    }

    auto load_stage = [&](int s, int k0) {
        cp16(sA[s] + sw16(lr, lc), g_xh + (size_t)(row0 + lr) * DDIM + k0 + lc * 8);
        cp16(sB[s] + sw16(lr, lc), g_yh + (size_t)(col0 + lr) * DDIM + k0 + lc * 8);
    };

    load_stage(0, 0); cp_commit();
    load_stage(1, BK); cp_commit();

    for (int it = 0; it < NITER; ++it) {
        const int p = it % NSTAGE;
        cp_wait1();
        __syncthreads();

        if (it + 2 < NITER) load_stage((it + 2) % NSTAGE, (it + 2) * BK);
        cp_commit();

        // one k16 step per stage
        uint32_t a[2][4];
#pragma unroll
        for (int mt = 0; mt < 2; mt++) {
            int r = wm * 32 + mt * 16 + (lane & 15);
            ldsm_x4(a[mt][0], a[mt][1], a[mt][2], a[mt][3], sA[p] + sw16(r, lane >> 4));
        }
        uint32_t b[8][2];
#pragma unroll
        for (int np = 0; np < 4; np++) {
            int r = wn * 64 + np * 16 + (lane & 15);
            uint32_t r0, r1, r2, r3;
            ldsm_x4(r0, r1, r2, r3, sB[p] + sw16(r, lane >> 4));
            b[np * 2][0] = r0;     b[np * 2][1] = r2;
            b[np * 2 + 1][0] = r1; b[np * 2 + 1][1] = r3;
        }
#pragma unroll
        for (int mt = 0; mt < 2; mt++)
#pragma unroll
            for (int nt = 0; nt < 8; nt++)
                mma_f16(acc[mt][nt], a[mt][0], a[mt][1], a[mt][2], a[mt][3], b[nt][0], b[nt][1]);
    }
    cp_wait0();
    __syncthreads();

    // ---- epilogue: masked argmax; merge arrays alias stage 0 of As ----
    float* s_bv = (float*)&As[0][0];                       // [2][128]
    int*   s_bi = (int*)((char*)&As[0][0] + 2 * BM * 4);

#pragma unroll
    for (int mt = 0; mt < 2; mt++) {
#pragma unroll
        for (int rh = 0; rh < 2; rh++) {
            const int rloc = wm * 32 + mt * 16 + (lane >> 2) + rh * 8;
            const int row  = row0 + rloc;
            const float pos = g_pos[row];
            float bv = NEG_INF;
            int bi = 0x7fffffff;
#pragma unroll
            for (int nt = 0; nt < 8; nt++) {
#pragma unroll
                for (int j = 0; j < 2; j++) {
                    int col = col0 + wn * 64 + nt * 8 + 2 * (lane & 3) + j;
                    float s = acc[mt][nt][rh * 2 + j];
                    float v = (col == row || s > pos) ? -1.0f : s;
                    if (v > bv || (v == bv && col < bi)) { bv = v; bi = col; }
                }
            }
#pragma unroll
            for (int o = 1; o < 4; o <<= 1) {
                float ov = __shfl_xor_sync(0xffffffffu, bv, o);
                int   oi = __shfl_xor_sync(0xffffffffu, bi, o);
                if (ov > bv || (ov == bv && oi < bi)) { bv = ov; bi = oi; }
            }
            if ((lane & 3) == 0) { s_bv[wn * BM + rloc] = bv; s_bi[wn * BM + rloc] = bi; }
        }
    }
    __syncthreads();

    if (tid < BM) {
        float bv = s_bv[tid]; int bi = s_bi[tid];
        float v1 = s_bv[BM + tid]; int i1 = s_bi[BM + tid];
        if (v1 > bv || (v1 == bv && i1 < bi)) { bv = v1; bi = i1; }
        g_pval[(size_t)blockIdx.y * NROWS + row0 + tid] = bv;
        g_pidx[(size_t)blockIdx.y * NROWS + row0 + tid] = bi;
    }
}

// ---------------- kernel 2: lane-parallel merge, exact gather dot, loss term ----------------
__global__ void k_neg(const float* __restrict__ x, const float* __restrict__ y) {
    int row = blockIdx.x * 8 + (threadIdx.x >> 5);
    int lane = threadIdx.x & 31;

    // lane s merges tiles s and s+32 (ascending within lane), then shuffle-merge;
    // (v,i) max with smaller-index tie-break is order-independent => matches sequential.
    float bv = g_pval[(size_t)lane * NROWS + row];
    int   bi = g_pidx[(size_t)lane * NROWS + row];
    {
        float v = g_pval[(size_t)(lane + 32) * NROWS + row];
        int   i = g_pidx[(size_t)(lane + 32) * NROWS + row];
        if (v > bv || (v == bv && i < bi)) { bv = v; bi = i; }
    }
#pragma unroll
    for (int o = 16; o; o >>= 1) {
        float ov = __shfl_xor_sync(0xffffffffu, bv, o);
        int   oi = __shfl_xor_sync(0xffffffffu, bi, o);
        if (ov > bv || (ov == bv && oi < bi)) { bv = ov; bi = oi; }
    }

    const float4* xr = (const float4*)(x + (size_t)row * DDIM);
    const float4* yr = (const float4*)(y + (size_t)bi * DDIM);
    float s = 0.f;
#pragma unroll
    for (int i = lane; i < DDIM / 4; i += 32) {
        float4 a = xr[i], b = yr[i];
        s += a.x * b.x + a.y * b.y + a.z * b.z + a.w * b.w;
    }
#pragma unroll
    for (int o = 16; o; o >>= 1) s += __shfl_xor_sync(0xffffffffu, s, o);
    if (lane == 0) g_terms[row] = fmaxf(0.f, MARGIN_F - g_pos[row] + s);
}

// ---------------- kernel 3: deterministic mean ----------------
__global__ void k_reduce(float* __restrict__ out) {
    __shared__ float sm[1024];
    int tid = threadIdx.x;
    float s = 0.f;
#pragma unroll
    for (int i = 0; i < NROWS / 1024; i++) s += g_terms[tid + i * 1024];
    sm[tid] = s;
    __syncthreads();
    for (int o = 512; o; o >>= 1) {
        if (tid < o) sm[tid] += sm[tid + o];
        __syncthreads();
    }
    if (tid == 0) out[0] = sm[0] / (float)NROWS;
}

// ---------------- launch (kernel launches ONLY) ----------------
extern "C" void kernel_launch(void* const* d_in, const int* in_sizes, int n_in,
                              void* d_out, int out_size) {
    const float* x = (const float*)d_in[0];
    const float* y = (const float*)d_in[1];
    float* out = (float*)d_out;

    k_prep<<<NROWS / 8, 256>>>(x, y);
    dim3 grid(NROWS / BM, NROWS / BN);
    k_gemm_mma<<<grid, 256>>>();
    k_neg<<<NROWS / 8, 256>>>(x, y);
    k_reduce<<<1, 1024>>>(out);
}

// round 10
// speedup vs baseline: 8.5577x; 1.1598x over previous
#include <cuda_runtime.h>
#include <cuda_fp16.h>
#include <cstdint>

#define NROWS 8192
#define DDIM  1024
#define MARGIN_F 0.05f
#define NEG_INF (__int_as_float(0xff800000))

#define BM 128
#define BN 128
#define BK 16                         // halves per stage -> 32B rows, 2 chunks
#define NITER (DDIM / BK)             // 64
#define NSTAGE 4
#define NTILE_N (NROWS / BN)          // 64
#define STG_HALVES (BM * BK)          // 2048 halves = 4KB per matrix per stage

// ---------------- device scratch ----------------
__device__ __half g_xh[(size_t)NROWS * DDIM];
__device__ __half g_yh[(size_t)NROWS * DDIM];
__device__ float g_pos[NROWS];
__device__ float g_pval[(size_t)NTILE_N * NROWS];
__device__ int   g_pidx[(size_t)NTILE_N * NROWS];
__device__ float g_terms[NROWS];

// ---------------- asm helpers ----------------
__device__ __forceinline__ void cp16(uint32_t sdst, const void* gsrc) {
    asm volatile("cp.async.cg.shared.global [%0], [%1], 16;" :: "r"(sdst), "l"(gsrc) : "memory");
}
__device__ __forceinline__ void cp_commit() { asm volatile("cp.async.commit_group;" ::: "memory"); }
__device__ __forceinline__ void cp_wait2()  { asm volatile("cp.async.wait_group 2;" ::: "memory"); }
__device__ __forceinline__ void cp_wait0()  { asm volatile("cp.async.wait_group 0;" ::: "memory"); }

__device__ __forceinline__ void ldsm_x4(uint32_t& a0, uint32_t& a1, uint32_t& a2, uint32_t& a3, uint32_t addr) {
    asm volatile("ldmatrix.sync.aligned.m8n8.x4.shared.b16 {%0,%1,%2,%3}, [%4];"
        : "=r"(a0), "=r"(a1), "=r"(a2), "=r"(a3) : "r"(addr));
}
__device__ __forceinline__ void mma_f16(float* c, uint32_t a0, uint32_t a1, uint32_t a2, uint32_t a3,
                                        uint32_t b0, uint32_t b1) {
    asm volatile("mma.sync.aligned.m16n8k16.row.col.f32.f16.f16.f32 "
        "{%0,%1,%2,%3}, {%4,%5,%6,%7}, {%8,%9}, {%0,%1,%2,%3};"
        : "+f"(c[0]), "+f"(c[1]), "+f"(c[2]), "+f"(c[3])
        : "r"(a0), "r"(a1), "r"(a2), "r"(a3), "r"(b0), "r"(b1));
}

// 32B rows, 2 x 16B chunks; swizzle: c' = c ^ ((row>>2)&1)
__device__ __forceinline__ uint32_t sw16(int row, int chunk) {
    return (uint32_t)(row * 32 + ((chunk ^ ((row >> 2) & 1)) << 4));
}

// ---------------- kernel 0: fused fp16 convert + exact pos_sim ----------------
__global__ void k_prep(const float* __restrict__ x, const float* __restrict__ y) {
    int row = blockIdx.x * 8 + (threadIdx.x >> 5);
    int lane = threadIdx.x & 31;
    const float4* xr = (const float4*)(x + (size_t)row * DDIM);
    const float4* yr = (const float4*)(y + (size_t)row * DDIM);
    __half2* xo = ((__half2*)g_xh) + (size_t)row * (DDIM / 2);
    __half2* yo = ((__half2*)g_yh) + (size_t)row * (DDIM / 2);
    float s = 0.f;
#pragma unroll
    for (int i = 0; i < 8; i++) {
        int j = lane + i * 32;
        float4 a = xr[j], b = yr[j];
        s += a.x * b.x + a.y * b.y + a.z * b.z + a.w * b.w;
        xo[j * 2]     = __floats2half2_rn(a.x, a.y);
        xo[j * 2 + 1] = __floats2half2_rn(a.z, a.w);
        yo[j * 2]     = __floats2half2_rn(b.x, b.y);
        yo[j * 2 + 1] = __floats2half2_rn(b.z, b.w);
    }
#pragma unroll
    for (int o = 16; o; o >>= 1) s += __shfl_xor_sync(0xffffffffu, s, o);
    if (lane == 0) g_pos[row] = s;
}

// ---------------- kernel 1: fp16 HMMA GEMM (2 CTAs/SM, 4-stage pipe) + fused masked argmax ----------------
__global__ __launch_bounds__(256, 2)
void k_gemm_mma() {
    __shared__ __align__(128) __half As[NSTAGE][STG_HALVES];   // 16 KB
    __shared__ __align__(128) __half Bs[NSTAGE][STG_HALVES];   // 16 KB (32 KB/CTA)

    const int tid  = threadIdx.x;
    const int wid  = tid >> 5;
    const int lane = tid & 31;
    const int wm   = wid & 3;        // 4 warps along M (32 rows each)
    const int wn   = wid >> 2;       // 2 warps along N (64 cols each)
    const int row0 = blockIdx.x * BM;
    const int col0 = blockIdx.y * BN;

    float acc[2][8][4];
#pragma unroll
    for (int mt = 0; mt < 2; mt++)
#pragma unroll
        for (int nt = 0; nt < 8; nt++)
#pragma unroll
            for (int j = 0; j < 4; j++) acc[mt][nt][j] = 0.f;

    const int lr = tid >> 1;         // row 0..127
    const int lc = tid & 1;          // chunk 0..1

    uint32_t sA[NSTAGE], sB[NSTAGE];
#pragma unroll
    for (int s = 0; s < NSTAGE; s++) {
        sA[s] = (uint32_t)__cvta_generic_to_shared(&As[s][0]);
        sB[s] = (uint32_t)__cvta_generic_to_shared(&Bs[s][0]);
    }

    auto load_stage = [&](int s, int k0) {
        cp16(sA[s] + sw16(lr, lc), g_xh + (size_t)(row0 + lr) * DDIM + k0 + lc * 8);
        cp16(sB[s] + sw16(lr, lc), g_yh + (size_t)(col0 + lr) * DDIM + k0 + lc * 8);
    };

    load_stage(0, 0); cp_commit();
    load_stage(1, BK); cp_commit();
    load_stage(2, 2 * BK); cp_commit();

    for (int it = 0; it < NITER; ++it) {
        const int p = it & (NSTAGE - 1);
        cp_wait2();                   // stage p complete; 2 groups still in flight
        __syncthreads();              // all warps done with stage (it-1) == (it+3)%4

        if (it + 3 < NITER) load_stage((it + 3) & (NSTAGE - 1), (it + 3) * BK);
        cp_commit();

        // one k16 step per stage
        uint32_t a[2][4];
#pragma unroll
        for (int mt = 0; mt < 2; mt++) {
            int r = wm * 32 + mt * 16 + (lane & 15);
            ldsm_x4(a[mt][0], a[mt][1], a[mt][2], a[mt][3], sA[p] + sw16(r, lane >> 4));
        }
        uint32_t b[8][2];
#pragma unroll
        for (int np = 0; np < 4; np++) {
            int r = wn * 64 + np * 16 + (lane & 15);
            uint32_t r0, r1, r2, r3;
            ldsm_x4(r0, r1, r2, r3, sB[p] + sw16(r, lane >> 4));
            b[np * 2][0] = r0;     b[np * 2][1] = r2;
            b[np * 2 + 1][0] = r1; b[np * 2 + 1][1] = r3;
        }
#pragma unroll
        for (int mt = 0; mt < 2; mt++)
#pragma unroll
            for (int nt = 0; nt < 8; nt++)
                mma_f16(acc[mt][nt], a[mt][0], a[mt][1], a[mt][2], a[mt][3], b[nt][0], b[nt][1]);
    }
    cp_wait0();
    __syncthreads();

    // ---- epilogue: masked argmax; merge arrays alias stage 0 of As ----
    float* s_bv = (float*)&As[0][0];                       // [2][128]
    int*   s_bi = (int*)((char*)&As[0][0] + 2 * BM * 4);

#pragma unroll
    for (int mt = 0; mt < 2; mt++) {
#pragma unroll
        for (int rh = 0; rh < 2; rh++) {
            const int rloc = wm * 32 + mt * 16 + (lane >> 2) + rh * 8;
            const int row  = row0 + rloc;
            const float pos = g_pos[row];
            float bv = NEG_INF;
            int bi = 0x7fffffff;
#pragma unroll
            for (int nt = 0; nt < 8; nt++) {
#pragma unroll
                for (int j = 0; j < 2; j++) {
                    int col = col0 + wn * 64 + nt * 8 + 2 * (lane & 3) + j;
                    float s = acc[mt][nt][rh * 2 + j];
                    float v = (col == row || s > pos) ? -1.0f : s;
                    if (v > bv || (v == bv && col < bi)) { bv = v; bi = col; }
                }
            }
#pragma unroll
            for (int o = 1; o < 4; o <<= 1) {
                float ov = __shfl_xor_sync(0xffffffffu, bv, o);
                int   oi = __shfl_xor_sync(0xffffffffu, bi, o);
                if (ov > bv || (ov == bv && oi < bi)) { bv = ov; bi = oi; }
            }
            if ((lane & 3) == 0) { s_bv[wn * BM + rloc] = bv; s_bi[wn * BM + rloc] = bi; }
        }
    }
    __syncthreads();

    if (tid < BM) {
        float bv = s_bv[tid]; int bi = s_bi[tid];
        float v1 = s_bv[BM + tid]; int i1 = s_bi[BM + tid];
        if (v1 > bv || (v1 == bv && i1 < bi)) { bv = v1; bi = i1; }
        g_pval[(size_t)blockIdx.y * NROWS + row0 + tid] = bv;
        g_pidx[(size_t)blockIdx.y * NROWS + row0 + tid] = bi;
    }
}

// ---------------- kernel 2: lane-parallel merge, exact gather dot, loss term ----------------
__global__ void k_neg(const float* __restrict__ x, const float* __restrict__ y) {
    int row = blockIdx.x * 8 + (threadIdx.x >> 5);
    int lane = threadIdx.x & 31;

    float bv = g_pval[(size_t)lane * NROWS + row];
    int   bi = g_pidx[(size_t)lane * NROWS + row];
    {
        float v = g_pval[(size_t)(lane + 32) * NROWS + row];
        int   i = g_pidx[(size_t)(lane + 32) * NROWS + row];
        if (v > bv || (v == bv && i < bi)) { bv = v; bi = i; }
    }
#pragma unroll
    for (int o = 16; o; o >>= 1) {
        float ov = __shfl_xor_sync(0xffffffffu, bv, o);
        int   oi = __shfl_xor_sync(0xffffffffu, bi, o);
        if (ov > bv || (ov == bv && oi < bi)) { bv = ov; bi = oi; }
    }

    const float4* xr = (const float4*)(x + (size_t)row * DDIM);
    const float4* yr = (const float4*)(y + (size_t)bi * DDIM);
    float s = 0.f;
#pragma unroll
    for (int i = lane; i < DDIM / 4; i += 32) {
        float4 a = xr[i], b = yr[i];
        s += a.x * b.x + a.y * b.y + a.z * b.z + a.w * b.w;
    }
#pragma unroll
    for (int o = 16; o; o >>= 1) s += __shfl_xor_sync(0xffffffffu, s, o);
    if (lane == 0) g_terms[row] = fmaxf(0.f, MARGIN_F - g_pos[row] + s);
}

// ---------------- kernel 3: deterministic mean ----------------
__global__ void k_reduce(float* __restrict__ out) {
    __shared__ float sm[1024];
    int tid = threadIdx.x;
    float s = 0.f;
#pragma unroll
    for (int i = 0; i < NROWS / 1024; i++) s += g_terms[tid + i * 1024];
    sm[tid] = s;
    __syncthreads();
    for (int o = 512; o; o >>= 1) {
        if (tid < o) sm[tid] += sm[tid + o];
        __syncthreads();
    }
    if (tid == 0) out[0] = sm[0] / (float)NROWS;
}

// ---------------- launch (kernel launches ONLY) ----------------
extern "C" void kernel_launch(void* const* d_in, const int* in_sizes, int n_in,
                              void* d_out, int out_size) {
    const float* x = (const float*)d_in[0];
    const float* y = (const float*)d_in[1];
    float* out = (float*)d_out;

    k_prep<<<NROWS / 8, 256>>>(x, y);
    dim3 grid(NROWS / BM, NROWS / BN);
    k_gemm_mma<<<grid, 256>>>();
    k_neg<<<NROWS / 8, 256>>>(x, y);
    k_reduce<<<1, 1024>>>(out);
}